// round 4
// baseline (speedup 1.0000x reference)
#include <cuda_runtime.h>

// 9-DoF alignment: per batch b,
//   cov = (x-mu_x)^T (y-mu_y)   [3x3]
//   R   = polar_rotation(cov)   (== U V^T from SVD, incl. det sign)
//   t   = mu_y - R mu_x
//   S   = ||yc||_F / (||xc||_F + 1e-6)
//
// One CTA per batch, 256 threads.
// Phase 1: warp-dense float4 streaming loads -> smem (4 lines per LDG).
// Phase 2: vector LDS.128 readback (3 float4 = 4 points per thread),
//          accumulate 11 sums, butterfly-reduce, serial 3x3 polar tail.

__global__ __launch_bounds__(256, 8)
void align9dof_kernel(const float* __restrict__ x,
                      const float* __restrict__ mu_x,
                      const float* __restrict__ y,
                      const float* __restrict__ mu_y,
                      float* __restrict__ out,
                      int B)
{
    __shared__ float4 s4x[768];
    __shared__ float4 s4y[768];
    __shared__ float  sh[8][11];

    const int b   = blockIdx.x;
    const int tid = threadIdx.x;

    // Per-batch means (broadcast loads)
    const float mx0 = mu_x[b * 3 + 0];
    const float mx1 = mu_x[b * 3 + 1];
    const float mx2 = mu_x[b * 3 + 2];
    const float my0 = mu_y[b * 3 + 0];
    const float my1 = mu_y[b * 3 + 1];
    const float my2 = mu_y[b * 3 + 2];

    // ---- Phase 1: dense streaming loads into smem (no transpose) ----
    const float4* __restrict__ xb = (const float4*)(x + (size_t)b * 3072);
    const float4* __restrict__ yb = (const float4*)(y + (size_t)b * 3072);

#pragma unroll
    for (int c = 0; c < 3; c++) {
        s4x[c * 256 + tid] = __ldcs(&xb[c * 256 + tid]);
        s4y[c * 256 + tid] = __ldcs(&yb[c * 256 + tid]);
    }
    __syncthreads();

    // ---- Phase 2: vector readback, 4 points per thread ----
    const float4 xa = s4x[3 * tid + 0];
    const float4 xm = s4x[3 * tid + 1];
    const float4 xc = s4x[3 * tid + 2];
    const float4 ya = s4y[3 * tid + 0];
    const float4 ym = s4y[3 * tid + 1];
    const float4 yc = s4y[3 * tid + 2];

    const float px[4][3] = {{xa.x, xa.y, xa.z}, {xa.w, xm.x, xm.y},
                            {xm.z, xm.w, xc.x}, {xc.y, xc.z, xc.w}};
    const float py[4][3] = {{ya.x, ya.y, ya.z}, {ya.w, ym.x, ym.y},
                            {ym.z, ym.w, yc.x}, {yc.y, yc.z, yc.w}};

    float v[11];  // c00..c22, sxx, syy
#pragma unroll
    for (int i = 0; i < 11; i++) v[i] = 0.0f;

#pragma unroll
    for (int p = 0; p < 4; p++) {
        const float u0 = px[p][0] - mx0, u1 = px[p][1] - mx1, u2 = px[p][2] - mx2;
        const float w0 = py[p][0] - my0, w1 = py[p][1] - my1, w2 = py[p][2] - my2;
        v[0] = fmaf(u0, w0, v[0]); v[1] = fmaf(u0, w1, v[1]); v[2] = fmaf(u0, w2, v[2]);
        v[3] = fmaf(u1, w0, v[3]); v[4] = fmaf(u1, w1, v[4]); v[5] = fmaf(u1, w2, v[5]);
        v[6] = fmaf(u2, w0, v[6]); v[7] = fmaf(u2, w1, v[7]); v[8] = fmaf(u2, w2, v[8]);
        v[9]  = fmaf(u0, u0, fmaf(u1, u1, fmaf(u2, u2, v[9])));
        v[10] = fmaf(w0, w0, fmaf(w1, w1, fmaf(w2, w2, v[10])));
    }

    // Warp butterfly reduction of 11 values
#pragma unroll
    for (int off = 16; off > 0; off >>= 1) {
#pragma unroll
        for (int i = 0; i < 11; i++)
            v[i] += __shfl_xor_sync(0xFFFFFFFFu, v[i], off);
    }

    const int lane = tid & 31;
    const int wrp  = tid >> 5;
    if (lane == 0) {
#pragma unroll
        for (int i = 0; i < 11; i++) sh[wrp][i] = v[i];
    }
    __syncthreads();

    if (tid == 0) {
        float A[9], sxx = 0.0f, syy = 0.0f;
#pragma unroll
        for (int i = 0; i < 9; i++) A[i] = 0.0f;
#pragma unroll
        for (int w = 0; w < 8; w++) {
#pragma unroll
            for (int i = 0; i < 9; i++) A[i] += sh[w][i];
            sxx += sh[w][9];
            syy += sh[w][10];
        }

        // ---- Orthogonal polar factor via determinant-scaled Newton ----
        float fro2 = 0.0f;
#pragma unroll
        for (int i = 0; i < 9; i++) fro2 = fmaf(A[i], A[i], fro2);
        const float invf = rsqrtf(fmaxf(fro2, 1e-30f));

        float X[9];
#pragma unroll
        for (int i = 0; i < 9; i++) X[i] = A[i] * invf;

#pragma unroll
        for (int it = 0; it < 8; it++) {
            float C[9];  // cofactor matrix: X^{-T} = C / det
            C[0] = X[4] * X[8] - X[5] * X[7];
            C[1] = X[5] * X[6] - X[3] * X[8];
            C[2] = X[3] * X[7] - X[4] * X[6];
            C[3] = X[2] * X[7] - X[1] * X[8];
            C[4] = X[0] * X[8] - X[2] * X[6];
            C[5] = X[1] * X[6] - X[0] * X[7];
            C[6] = X[1] * X[5] - X[2] * X[4];
            C[7] = X[2] * X[3] - X[0] * X[5];
            C[8] = X[0] * X[4] - X[1] * X[3];
            float det = X[0] * C[0] + X[1] * C[1] + X[2] * C[2];
            float ad  = fmaxf(fabsf(det), 1e-30f);
            float eta = rcbrtf(ad);            // |det|^{-1/3}
            float k1  = 0.5f * eta;
            float k2  = 0.5f / (eta * det);    // keeps det's sign
#pragma unroll
            for (int i = 0; i < 9; i++) X[i] = k1 * X[i] + k2 * C[i];
        }

        // t = mu_y - R mu_x
        const float t0 = my0 - (X[0] * mx0 + X[1] * mx1 + X[2] * mx2);
        const float t1 = my1 - (X[3] * mx0 + X[4] * mx1 + X[5] * mx2);
        const float t2 = my2 - (X[6] * mx0 + X[7] * mx1 + X[8] * mx2);

        const float xn = sqrtf(sxx);
        const float yn = sqrtf(syy);
        const float sf = yn / (xn + 1e-6f);

        // Output layout: [R (B*9)] [t (B*3)] [S (B)]
        float* __restrict__ Rout = out + (size_t)b * 9;
#pragma unroll
        for (int i = 0; i < 9; i++) Rout[i] = X[i];
        float* __restrict__ tout = out + (size_t)B * 9 + (size_t)b * 3;
        tout[0] = t0; tout[1] = t1; tout[2] = t2;
        out[(size_t)B * 12 + b] = sf;
    }
}

extern "C" void kernel_launch(void* const* d_in, const int* in_sizes, int n_in,
                              void* d_out, int out_size)
{
    const float* x    = (const float*)d_in[0];
    const float* mu_x = (const float*)d_in[1];
    const float* y    = (const float*)d_in[2];
    const float* mu_y = (const float*)d_in[3];
    float* out        = (float*)d_out;

    const int B = in_sizes[1] / 3;  // mu_x is [B,3]

    align9dof_kernel<<<B, 256>>>(x, mu_x, y, mu_y, out, B);
}

// round 5
// speedup vs baseline: 1.3003x; 1.3003x over previous
#include <cuda_runtime.h>

// 9-DoF alignment, one WARP per batch (no smem, no barriers).
//   cov = (x-mu_x)^T (y-mu_y); R = polar_rotation(cov) (== U V^T, incl. sign)
//   t = mu_y - R mu_x; S = ||yc||_F / (||xc||_F + 1e-6)
// Lane l handles 32 points: 8 groups x (3 consecutive float4 = 4 points).

__global__ __launch_bounds__(256)
void align9dof_kernel(const float* __restrict__ x,
                      const float* __restrict__ mu_x,
                      const float* __restrict__ y,
                      const float* __restrict__ mu_y,
                      float* __restrict__ out,
                      int B)
{
    const int warp = threadIdx.x >> 5;
    const int lane = threadIdx.x & 31;
    const int b    = blockIdx.x * 8 + warp;
    if (b >= B) return;

    // Per-batch means (uniform broadcast loads)
    const float mx0 = mu_x[b * 3 + 0];
    const float mx1 = mu_x[b * 3 + 1];
    const float mx2 = mu_x[b * 3 + 2];
    const float my0 = mu_y[b * 3 + 0];
    const float my1 = mu_y[b * 3 + 1];
    const float my2 = mu_y[b * 3 + 2];

    const float4* __restrict__ xb = (const float4*)(x + (size_t)b * 3072);
    const float4* __restrict__ yb = (const float4*)(y + (size_t)b * 3072);

    float v[11];  // c00..c22, sxx, syy
#pragma unroll
    for (int i = 0; i < 11; i++) v[i] = 0.0f;

#pragma unroll
    for (int g = 0; g < 8; g++) {
        const int base = g * 96 + 3 * lane;
        const float4 xa = __ldcs(&xb[base + 0]);
        const float4 xm = __ldcs(&xb[base + 1]);
        const float4 xc = __ldcs(&xb[base + 2]);
        const float4 ya = __ldcs(&yb[base + 0]);
        const float4 ym = __ldcs(&yb[base + 1]);
        const float4 yc = __ldcs(&yb[base + 2]);

        const float px[4][3] = {{xa.x, xa.y, xa.z}, {xa.w, xm.x, xm.y},
                                {xm.z, xm.w, xc.x}, {xc.y, xc.z, xc.w}};
        const float py[4][3] = {{ya.x, ya.y, ya.z}, {ya.w, ym.x, ym.y},
                                {ym.z, ym.w, yc.x}, {yc.y, yc.z, yc.w}};

#pragma unroll
        for (int p = 0; p < 4; p++) {
            const float u0 = px[p][0] - mx0, u1 = px[p][1] - mx1, u2 = px[p][2] - mx2;
            const float w0 = py[p][0] - my0, w1 = py[p][1] - my1, w2 = py[p][2] - my2;
            v[0] = fmaf(u0, w0, v[0]); v[1] = fmaf(u0, w1, v[1]); v[2] = fmaf(u0, w2, v[2]);
            v[3] = fmaf(u1, w0, v[3]); v[4] = fmaf(u1, w1, v[4]); v[5] = fmaf(u1, w2, v[5]);
            v[6] = fmaf(u2, w0, v[6]); v[7] = fmaf(u2, w1, v[7]); v[8] = fmaf(u2, w2, v[8]);
            v[9]  = fmaf(u0, u0, fmaf(u1, u1, fmaf(u2, u2, v[9])));
            v[10] = fmaf(w0, w0, fmaf(w1, w1, fmaf(w2, w2, v[10])));
        }
    }

    // Warp butterfly reduction: all lanes end with the full batch sums
#pragma unroll
    for (int off = 16; off > 0; off >>= 1) {
#pragma unroll
        for (int i = 0; i < 11; i++)
            v[i] += __shfl_xor_sync(0xFFFFFFFFu, v[i], off);
    }

    // ---- Polar factor via determinant-scaled Newton (all lanes, redundant) ----
    float fro2 = 0.0f;
#pragma unroll
    for (int i = 0; i < 9; i++) fro2 = fmaf(v[i], v[i], fro2);
    const float invf = rsqrtf(fmaxf(fro2, 1e-30f));

    float X[9];
#pragma unroll
    for (int i = 0; i < 9; i++) X[i] = v[i] * invf;

#pragma unroll
    for (int it = 0; it < 8; it++) {
        float C[9];  // cofactor matrix: X^{-T} = C / det
        C[0] = X[4] * X[8] - X[5] * X[7];
        C[1] = X[5] * X[6] - X[3] * X[8];
        C[2] = X[3] * X[7] - X[4] * X[6];
        C[3] = X[2] * X[7] - X[1] * X[8];
        C[4] = X[0] * X[8] - X[2] * X[6];
        C[5] = X[1] * X[6] - X[0] * X[7];
        C[6] = X[1] * X[5] - X[2] * X[4];
        C[7] = X[2] * X[3] - X[0] * X[5];
        C[8] = X[0] * X[4] - X[1] * X[3];
        float det = X[0] * C[0] + X[1] * C[1] + X[2] * C[2];
        float ad  = fmaxf(fabsf(det), 1e-30f);
        float eta = rcbrtf(ad);            // |det|^{-1/3}
        float k1  = 0.5f * eta;
        float k2  = 0.5f / (eta * det);    // keeps det's sign
#pragma unroll
        for (int i = 0; i < 9; i++) X[i] = k1 * X[i] + k2 * C[i];
    }

    // t = mu_y - R mu_x
    const float t0 = my0 - (X[0] * mx0 + X[1] * mx1 + X[2] * mx2);
    const float t1 = my1 - (X[3] * mx0 + X[4] * mx1 + X[5] * mx2);
    const float t2 = my2 - (X[6] * mx0 + X[7] * mx1 + X[8] * mx2);

    const float sf = sqrtf(v[10]) / (sqrtf(v[9]) + 1e-6f);

    // ---- Coalesced predicated stores (select-chains, no reg-indexed arrays) ----
    // R: lanes 0..8 each store one element
    if (lane < 9) {
        float r = (lane == 0) ? X[0] :
                  (lane == 1) ? X[1] :
                  (lane == 2) ? X[2] :
                  (lane == 3) ? X[3] :
                  (lane == 4) ? X[4] :
                  (lane == 5) ? X[5] :
                  (lane == 6) ? X[6] :
                  (lane == 7) ? X[7] : X[8];
        out[(size_t)b * 9 + lane] = r;
    }
    // t: lanes 0..2
    if (lane < 3) {
        float tv = (lane == 0) ? t0 : (lane == 1) ? t1 : t2;
        out[(size_t)B * 9 + (size_t)b * 3 + lane] = tv;
    }
    // S: lane 0
    if (lane == 0) {
        out[(size_t)B * 12 + b] = sf;
    }
}

extern "C" void kernel_launch(void* const* d_in, const int* in_sizes, int n_in,
                              void* d_out, int out_size)
{
    const float* x    = (const float*)d_in[0];
    const float* mu_x = (const float*)d_in[1];
    const float* y    = (const float*)d_in[2];
    const float* mu_y = (const float*)d_in[3];
    float* out        = (float*)d_out;

    const int B = in_sizes[1] / 3;  // mu_x is [B,3]

    align9dof_kernel<<<(B + 7) / 8, 256>>>(x, mu_x, y, mu_y, out, B);
}